// round 17
// baseline (speedup 1.0000x reference)
#include <cuda_runtime.h>
#include <cuda_fp16.h>
#include <cstdint>

#define LOG2E_F 1.44269504088896340736f

constexpr int Bz = 2, SQ = 2048, SKV = 2048, HQ = 16, HKV = 4, DH = 128;
constexpr int BR = 64, BC = 128, NT = 128;
constexpr int NTILE = SKV / BC;              // 16 kv tiles per (b,hk)

// fp16 smem strides (in half units)
constexpr int KSTR_H  = 144;   // K row: 128 halves + pad (72 words mod 32 = 8)
constexpr int VTSTR_H = 144;   // V^T row: 128 halves + pad
constexpr int K_TILE_BYTES = BC * KSTR_H * 2;     // 36864
constexpr int V_TILE_BYTES = DH * VTSTR_H * 2;    // 36864
// K double-buffered + V single: 110592 B/CTA -> 2 CTAs/SM (221 KB of 228)
constexpr size_t SMEM_BYTES = 2 * K_TILE_BYTES + V_TILE_BYTES;

// packed K: [b][hk][tile128][kv(128)][144h] fp16, 16-block interleave on dh
__device__ __half2 g_kc[(size_t)Bz * HKV * NTILE * BC * (KSTR_H / 2)];
// packed V^T: [b][hk][tile128][d(128)][144h] fp16, 16-block interleave on kv
__device__ __half g_vtc[(size_t)Bz * HKV * NTILE * DH * VTSTR_H];

// ---------------- helpers ----------------
__device__ __forceinline__ float ex2f(float x) {
    float y;
    asm("ex2.approx.f32 %0, %1;" : "=f"(y) : "f"(x));
    return y;
}
__device__ __forceinline__ uint32_t smem_u32(const void* p) {
    uint32_t a;
    asm("{ .reg .u64 t; cvta.to.shared.u64 t, %1; cvt.u32.u64 %0, t; }"
        : "=r"(a) : "l"(p));
    return a;
}
__device__ __forceinline__ void cpa16(uint32_t dst, const void* src) {
    asm volatile("cp.async.cg.shared.global [%0], [%1], 16;"
                 :: "r"(dst), "l"(src));
}
__device__ __forceinline__ void cpa_commit() {
    asm volatile("cp.async.commit_group;" ::: "memory");
}
__device__ __forceinline__ void cpa_wait0() {
    asm volatile("cp.async.wait_group 0;" ::: "memory");
}
__device__ __forceinline__ void cpa_wait1() {
    asm volatile("cp.async.wait_group 1;" ::: "memory");
}
__device__ __forceinline__ uint32_t packh2(float lo, float hi) {
    __half2 h = __floats2half2_rn(lo, hi);
    return *reinterpret_cast<uint32_t*>(&h);
}
// m16n8k16 row.col fp16 mma, fp32 accumulate
__device__ __forceinline__ void mma16(float* c, const uint32_t* a, uint2 b) {
    asm volatile(
        "mma.sync.aligned.m16n8k16.row.col.f32.f16.f16.f32 "
        "{%0,%1,%2,%3}, {%4,%5,%6,%7}, {%8,%9}, {%0,%1,%2,%3};\n"
        : "+f"(c[0]), "+f"(c[1]), "+f"(c[2]), "+f"(c[3])
        : "r"(a[0]), "r"(a[1]), "r"(a[2]), "r"(a[3]), "r"(b.x), "r"(b.y));
}
// 16-block interleave: pos(k) = 4*((k>>1)&3) + (k&1) + 2*((k>>3)&1) within block
__device__ __forceinline__ int vperm16(int k) {
    return (k & ~15) + 4 * ((k >> 1) & 3) + (k & 1) + 2 * ((k >> 3) & 1);
}

// ---------------- prepass: K pack (fp16, 16-block interleave on dh) --------
__global__ void kprep_kernel(const float* __restrict__ k) {
    int idx = blockIdx.x * 256 + threadIdx.x;     // one float4 each
    int d  = (idx & 31) * 4;
    int t  = idx >> 5;
    int hk = t & 3;  t >>= 2;
    int s  = t & (SKV - 1);
    int b  = t >> 11;
    float4 v4 = *(const float4*)(k + (((size_t)b * SKV + s) * HKV + hk) * DH + d);
    __half2* dst = g_kc + (((size_t)(b * HKV + hk) * NTILE + (s >> 7)) * BC
                           + (s & 127)) * (KSTR_H / 2) + (d & ~15) / 2;
    const int c = (d >> 2) & 3;
    int a0 = (c == 0) ? 0 : (c == 1) ? 4 : (c == 2) ? 1 : 5;
    dst[a0]     = __floats2half2_rn(v4.x, v4.y);
    dst[a0 + 2] = __floats2half2_rn(v4.z, v4.w);
}

// ---------------- prepass: V transpose+pack (fp16, interleave on kv) -------
__global__ void vtprep_kernel(const float* __restrict__ v) {
    __shared__ float t[64][33];
    const int kvt = blockIdx.x;          // kv sub-tile (64 wide)
    const int d0  = blockIdx.y * 32;
    const int bh  = blockIdx.z;          // b*HKV+hk
    const int b = bh >> 2, hk = bh & 3;
    const int tx = threadIdx.x, ty = threadIdx.y;   // 32 x 8
    const float* src = v + ((size_t)b * SKV * HKV + hk) * DH + d0;
    #pragma unroll
    for (int i = 0; i < 8; ++i) {
        int kvl = ty + 8 * i;
        t[kvl][tx] = src[(size_t)(kvt * 64 + kvl) * (HKV * DH) + tx];
    }
    __syncthreads();
    __half* dst = g_vtc + ((size_t)bh * NTILE + (kvt >> 1)) * (DH * VTSTR_H)
                + (size_t)d0 * VTSTR_H;
    const int kvbase = (kvt & 1) * 64;
    #pragma unroll
    for (int i = 0; i < 8; ++i) {
        int e = i * 256 + ty * 32 + tx;
        int dl = e >> 6, kvl = e & 63;
        dst[dl * VTSTR_H + vperm16(kvbase + kvl)] = __float2half_rn(t[kvl][dl]);
    }
}

// ---------------- main attention kernel ----------------
__global__ void __launch_bounds__(NT, 2)
fa_kernel(const float* __restrict__ q,
          const float* __restrict__ mask,
          float* __restrict__ out)
{
    extern __shared__ char sma[];
    __half* Kb[2] = { (__half*)sma, (__half*)(sma + K_TILE_BYTES) };
    __half* Vs = (__half*)(sma + 2 * K_TILE_BYTES);
    const uint32_t KBuf[2] = { smem_u32(Kb[0]), smem_u32(Kb[1]) };
    const uint32_t VBuf = smem_u32(Vs);

    const int tid = threadIdx.x;
    const int w = tid >> 5;            // 4 warps, warp owns rows w*16..w*16+15
    const int lane = tid & 31;
    const int qgrp = lane >> 2;
    const int qid  = lane & 3;

    const int bx = (int)gridDim.x - 1 - (int)blockIdx.x;   // big-first order
    const int q0 = bx * BR;
    const int h  = blockIdx.y;
    const int b  = blockIdx.z;
    const int hk = h & (HKV - 1);
    const int bh = b * HKV + hk;
    const int ntiles = (64 * bx + 191) >> 7;   // 128-wide tiles covering causal range

    const __half2* kc0 = g_kc + (size_t)bh * NTILE * (BC * (KSTR_H / 2));
    const __half*  vc0 = g_vtc + (size_t)bh * NTILE * (DH * VTSTR_H);

    // ---- prologue: issue K_0 into buffer 0 ----
    #pragma unroll
    for (int i = 0; i < 18; ++i) {
        int idx = tid + NT * i;
        cpa16(KBuf[0] + idx * 16, (const char*)kc0 + idx * 16);
    }
    cpa_commit();

    const int rg0 = q0 + w * 16 + qgrp;      // global row (and rg0+8)
    const int rwmax = q0 + w * 16 + 15;      // causal warp bound

    // ---- Q A-fragments (fp16, scaled) into registers ----
    uint32_t qA[8][4];
    {
        const float qs = LOG2E_F * 0.08838834764831845f;  // log2e/sqrt(128)
        const float* qb0 = q + (((size_t)b * SQ + rg0) * HQ + h) * DH;
        const float* qb1 = qb0 + (size_t)8 * HQ * DH;
        #pragma unroll
        for (int t = 0; t < 8; ++t) {
            const int c0 = t * 16 + 2 * qid;
            float2 f0 = *(const float2*)(qb0 + c0);
            float2 f1 = *(const float2*)(qb0 + c0 + 8);
            float2 f2 = *(const float2*)(qb1 + c0);
            float2 f3 = *(const float2*)(qb1 + c0 + 8);
            qA[t][0] = packh2(f0.x * qs, f0.y * qs);
            qA[t][1] = packh2(f2.x * qs, f2.y * qs);
            qA[t][2] = packh2(f1.x * qs, f1.y * qs);
            qA[t][3] = packh2(f3.x * qs, f3.y * qs);
        }
    }

    const float* mrow0 = mask + ((size_t)(b * HQ + h) * SQ + rg0) * SKV;
    const float* mrow1 = mrow0 + (size_t)8 * SKV;

    float O[16][4];
    #pragma unroll
    for (int nt = 0; nt < 16; ++nt) {
        O[nt][0] = 0.f; O[nt][1] = 0.f; O[nt][2] = 0.f; O[nt][3] = 0.f;
    }
    float ls0 = 0.f, ls1 = 0.f;

    for (int j = 0; j < ntiles; ++j) {
        const int kv0 = j * BC;
        const int cur = j & 1, nxt = cur ^ 1;
        const __half* Ks = Kb[cur];

        cpa_wait0();                 // K_j resident (sole pending group)
        __syncthreads();             // publish K_j; proves MMA2_{j-1} done (V free)
                                     // and MMA1_{j-1} done (K buffer nxt free)

        // ---- issue V_j, then K_{j+1} (other K buffer -> no WAR with MMA1) --
        {
            const char* vs = (const char*)(vc0 + (size_t)j * (DH * VTSTR_H));
            #pragma unroll
            for (int i = 0; i < 18; ++i) {
                int idx = tid + NT * i;
                cpa16(VBuf + idx * 16, vs + idx * 16);
            }
        }
        cpa_commit();                // group: V_j
        if (j + 1 < ntiles) {
            const char* ks = (const char*)(kc0 + (size_t)(j + 1) * (BC * (KSTR_H / 2)));
            #pragma unroll
            for (int i = 0; i < 18; ++i) {
                int idx = tid + NT * i;
                cpa16(KBuf[nxt] + idx * 16, ks + idx * 16);
            }
        }
        cpa_commit();                // group: K_{j+1} (possibly empty)

        // ---- S = Q@K^T + softmax, processed in two 64-kv halves ----
        float S[16][4];
        #pragma unroll
        for (int half = 0; half < 2; ++half) {
            const int kvh = kv0 + half * 64;
            float* Sh0 = &S[half * 8][0];
            if (kvh <= rwmax) {
                float2 mk0[8], mk1[8];
                #pragma unroll
                for (int nt = 0; nt < 8; ++nt) {
                    mk0[nt] = *(const float2*)(mrow0 + kvh + nt * 8 + 2 * qid);
                    mk1[nt] = *(const float2*)(mrow1 + kvh + nt * 8 + 2 * qid);
                }
                #pragma unroll
                for (int nt = 0; nt < 8; ++nt) {
                    Sh0[nt * 4 + 0] = 0.f; Sh0[nt * 4 + 1] = 0.f;
                    Sh0[nt * 4 + 2] = 0.f; Sh0[nt * 4 + 3] = 0.f;
                }
                #pragma unroll
                for (int t = 0; t < 8; ++t) {            // dh 16-blocks
                    #pragma unroll
                    for (int nt = 0; nt < 8; ++nt) {     // kv n8-blocks
                        uint2 bb = *(const uint2*)(Ks + (half * 64 + nt * 8 + qgrp) * KSTR_H
                                                   + t * 16 + 4 * qid);
                        mma16(&Sh0[nt * 4], qA[t], bb);
                    }
                }
                #pragma unroll
                for (int nt = 0; nt < 8; ++nt) {
                    const int c0 = kvh + nt * 8 + 2 * qid;
                    float p00 = (c0     <= rg0)     ? ex2f(Sh0[nt*4+0] + LOG2E_F * mk0[nt].x) : 0.f;
                    float p01 = (c0 + 1 <= rg0)     ? ex2f(Sh0[nt*4+1] + LOG2E_F * mk0[nt].y) : 0.f;
                    float p10 = (c0     <= rg0 + 8) ? ex2f(Sh0[nt*4+2] + LOG2E_F * mk1[nt].x) : 0.f;
                    float p11 = (c0 + 1 <= rg0 + 8) ? ex2f(Sh0[nt*4+3] + LOG2E_F * mk1[nt].y) : 0.f;
                    ls0 += p00 + p01;
                    ls1 += p10 + p11;
                    Sh0[nt*4+0] = p00; Sh0[nt*4+1] = p01;
                    Sh0[nt*4+2] = p10; Sh0[nt*4+3] = p11;
                }
            } else {
                #pragma unroll
                for (int nt = 0; nt < 8; ++nt) {
                    Sh0[nt * 4 + 0] = 0.f; Sh0[nt * 4 + 1] = 0.f;
                    Sh0[nt * 4 + 2] = 0.f; Sh0[nt * 4 + 3] = 0.f;
                }
            }
        }

        cpa_wait1();                 // V_j done (K_{j+1} is the 1 exempt group)
        __syncthreads();             // publish V_j

        // ---- MMA2: O(m16 x d128) += P @ V over 128 kv (causally guarded) ---
        #pragma unroll
        for (int t = 0; t < 8; ++t) {            // kv 16-blocks
            if (kv0 + t * 16 <= rwmax) {         // warp-uniform guard
                uint32_t pA[4];
                pA[0] = packh2(S[2 * t][0],     S[2 * t][1]);
                pA[1] = packh2(S[2 * t][2],     S[2 * t][3]);
                pA[2] = packh2(S[2 * t + 1][0], S[2 * t + 1][1]);
                pA[3] = packh2(S[2 * t + 1][2], S[2 * t + 1][3]);
                #pragma unroll
                for (int nt = 0; nt < 16; ++nt) {    // d n8-blocks
                    uint2 bb = *(const uint2*)(Vs + (nt * 8 + qgrp) * VTSTR_H
                                               + t * 16 + 4 * qid);
                    mma16(O[nt], pA, bb);
                }
            }
        }
    }

    // ---- row sums (reduce over qid lanes), normalize, store ----
    ls0 += __shfl_xor_sync(0xffffffffu, ls0, 1);
    ls0 += __shfl_xor_sync(0xffffffffu, ls0, 2);
    ls1 += __shfl_xor_sync(0xffffffffu, ls1, 1);
    ls1 += __shfl_xor_sync(0xffffffffu, ls1, 2);
    const float inv0 = 1.0f / ls0;
    const float inv1 = 1.0f / ls1;

    float* o0 = out + (((size_t)b * SQ + rg0) * HQ + h) * DH;
    float* o1 = o0 + (size_t)8 * HQ * DH;
    #pragma unroll
    for (int nt = 0; nt < 16; ++nt) {
        const int c = nt * 8 + 2 * qid;
        *(float2*)(o0 + c) = make_float2(O[nt][0] * inv0, O[nt][1] * inv0);
        *(float2*)(o1 + c) = make_float2(O[nt][2] * inv1, O[nt][3] * inv1);
    }
}

extern "C" void kernel_launch(void* const* d_in, const int* in_sizes, int n_in,
                              void* d_out, int out_size) {
    (void)in_sizes; (void)n_in; (void)out_size;
    const float* q = (const float*)d_in[0];
    const float* k = (const float*)d_in[1];
    const float* v = (const float*)d_in[2];
    const float* mask = (const float*)d_in[3];
    float* out = (float*)d_out;

    cudaFuncSetAttribute(fa_kernel,
                         cudaFuncAttributeMaxDynamicSharedMemorySize,
                         (int)SMEM_BYTES);

    kprep_kernel<<<(Bz * SKV * HKV * DH / 4) / 256, 256>>>(k);
    vtprep_kernel<<<dim3(SKV / 64, DH / 32, Bz * HKV), dim3(32, 8)>>>(v);
    fa_kernel<<<dim3(SQ / BR, HQ, Bz), NT, SMEM_BYTES>>>(q, mask, out);
}